// round 10
// baseline (speedup 1.0000x reference)
#include <cuda_runtime.h>
#include <cuda_bf16.h>
#include <cstdint>

#define NN 512      // tokens
#define DN 256      // d_node
#define DE 128      // d_edge
#define DH 32       // d_head
#define LN_EPS 1e-5f

// Scratch (device globals: no allocation allowed)
__device__ float g_left[NN * DH];
__device__ float g_right[NN * DH];
__device__ float g_T[NN * DH * DE];   // [n][j][e] = [512][32][128]

// ---------------- bf16 hi/lo pack ----------------
__device__ __forceinline__ uint32_t pack_bf2(float x0, float x1, uint32_t& lo_pack) {
    __nv_bfloat16 h0 = __float2bfloat16(x0);
    __nv_bfloat16 h1 = __float2bfloat16(x1);
    __nv_bfloat16 l0 = __float2bfloat16(x0 - __bfloat162float(h0));
    __nv_bfloat16 l1 = __float2bfloat16(x1 - __bfloat162float(h1));
    uint32_t hp = (uint32_t)__bfloat16_as_ushort(h0) |
                  ((uint32_t)__bfloat16_as_ushort(h1) << 16);
    lo_pack = (uint32_t)__bfloat16_as_ushort(l0) |
              ((uint32_t)__bfloat16_as_ushort(l1) << 16);
    return hp;
}

// mma.sync m16n8k16 row.col bf16 -> f32 accumulate (baseline PTX, sm_80+)
__device__ __forceinline__ void mma16816(float* c, const uint32_t* a,
                                         uint32_t b0, uint32_t b1) {
    asm volatile(
        "mma.sync.aligned.m16n8k16.row.col.f32.bf16.bf16.f32 "
        "{%0,%1,%2,%3}, {%4,%5,%6,%7}, {%8,%9}, {%0,%1,%2,%3};"
        : "+f"(c[0]), "+f"(c[1]), "+f"(c[2]), "+f"(c[3])
        : "r"(a[0]), "r"(a[1]), "r"(a[2]), "r"(a[3]), "r"(b0), "r"(b1));
}

// ---------------- P1: LayerNorm + left/right projections ----------------
__global__ void p1_kernel(const float* __restrict__ node,
                          const float* __restrict__ ln_w,
                          const float* __restrict__ ln_b,
                          const float* __restrict__ wl,
                          const float* __restrict__ bl,
                          const float* __restrict__ wr,
                          const float* __restrict__ br) {
    __shared__ float xs[DN];
    __shared__ float2 red[8];
    __shared__ float ps[4][64];

    int n = blockIdx.x;
    int tid = threadIdx.x;
    float v = node[n * DN + tid];

    float s = v, q = v * v;
    #pragma unroll
    for (int o = 16; o; o >>= 1) {
        s += __shfl_xor_sync(0xffffffffu, s, o);
        q += __shfl_xor_sync(0xffffffffu, q, o);
    }
    if ((tid & 31) == 0) red[tid >> 5] = make_float2(s, q);
    __syncthreads();
    float S = 0.f, Q = 0.f;
    #pragma unroll
    for (int i = 0; i < 8; i++) { S += red[i].x; Q += red[i].y; }
    float mu = S * (1.f / 256.f);
    float var = Q * (1.f / 256.f) - mu * mu;
    float rstd = rsqrtf(var + LN_EPS);

    xs[tid] = (v - mu) * rstd * ln_w[tid] + ln_b[tid];
    __syncthreads();

    int h = tid & 31;
    int sel = (tid >> 5) & 1;
    int part = tid >> 6;
    const float* __restrict__ w = sel ? wr : wl;
    int k0 = part * 64;
    float a0 = 0.f, a1 = 0.f, a2 = 0.f, a3 = 0.f;
    #pragma unroll 4
    for (int k = 0; k < 64; k += 4) {
        a0 += xs[k0 + k + 0] * w[(k0 + k + 0) * DH + h];
        a1 += xs[k0 + k + 1] * w[(k0 + k + 1) * DH + h];
        a2 += xs[k0 + k + 2] * w[(k0 + k + 2) * DH + h];
        a3 += xs[k0 + k + 3] * w[(k0 + k + 3) * DH + h];
    }
    ps[part][sel * 32 + h] = (a0 + a1) + (a2 + a3);
    __syncthreads();

    if (tid < 64) {
        float r = ps[0][tid] + ps[1][tid] + ps[2][tid] + ps[3][tid];
        if (tid < 32) g_left[n * DH + tid] = r + bl[tid];
        else          g_right[n * DH + (tid - 32)] = r + br[tid - 32];
    }
}

// ---------------- P2: T = left @ w_out (viewed [32][4096]) ----------------
__global__ void p2_kernel(const float* __restrict__ w_out) {
    __shared__ float As[32 * 32];

    int nb = blockIdx.y * 32;
    int cb = blockIdx.x * 128;
    int tid = threadIdx.x;

    {
        int row = tid >> 3, qq = tid & 7;
        *(float4*)&As[row * 32 + qq * 4] =
            *(const float4*)(g_left + (nb + row) * DH + qq * 4);
    }
    __syncthreads();

    int col = cb + (tid & 127);
    int nset = tid >> 7;
    float acc[16];
    #pragma unroll
    for (int r = 0; r < 16; r++) acc[r] = 0.f;

    #pragma unroll 4
    for (int i = 0; i < 32; i++) {
        float b = w_out[i * 4096 + col];
        #pragma unroll
        for (int r = 0; r < 16; r++)
            acc[r] += As[(nset * 16 + r) * 32 + i] * b;
    }

    #pragma unroll
    for (int r = 0; r < 16; r++)
        g_T[(nb + nset * 16 + r) * (DH * DE) + col] = acc[r];
}

// ---------------- Main kernel: out = edge + b_out + right @ T (HMMA) ------
// 64m x 128e tile, 256 threads, 4 blocks/SM (32 warps). Warp tile 16m x 64e.
// A (right) bf16 hi/lo fragments in regs; B (T[n]) staged to smem transposed
// [e][j] packed bf16 hi/lo (pitch 17). 3 products (AhiBhi+AhiBlo+AloBhi),
// fp32 accum -> rel err ~3e-6. Tensor pipe does the math; LSU streams edge/out.
#define BPITCH 17
__global__ void __launch_bounds__(256, 4)
outk_kernel(const float* __restrict__ edge,
            const float* __restrict__ b_out,
            float* __restrict__ out) {
    __shared__ uint32_t sBh[128 * BPITCH];
    __shared__ uint32_t sBl[128 * BPITCH];
    __shared__ float sbias[DE];

    int tid = threadIdx.x;
    int w = tid >> 5, lane = tid & 31;
    int g = lane >> 2, tig = lane & 3;
    int n = blockIdx.y;
    int m_base = blockIdx.x * 64;
    int m0 = (w >> 1) * 16;          // warp's 16 m rows within tile
    int ehalf = (w & 1) * 64;        // warp's 64 e columns

    if (tid < DE) sbias[tid] = b_out[tid];

    // stage T[n] -> smem transposed [e][j-pair] bf16 hi/lo (coalesced reads)
    {
        int se = tid & 127;
        int q = tid >> 7;            // 0..1 -> 8 j-pairs each
        const float* tn = g_T + (size_t)n * (DH * DE);
        #pragma unroll
        for (int r = 0; r < 8; r++) {
            int jp = q * 8 + r;
            float x0 = __ldg(tn + (2 * jp) * DE + se);
            float x1 = __ldg(tn + (2 * jp + 1) * DE + se);
            uint32_t lp, hp = pack_bf2(x0, x1, lp);
            sBh[se * BPITCH + jp] = hp;
            sBl[se * BPITCH + jp] = lp;
        }
    }

    // A fragments (once per block): right[m_base+m0..+16][0..32) hi/lo
    uint32_t Ah[2][4], Al[2][4];
    {
        const float* r0 = g_right + (m_base + m0 + g) * DH;
        const float* r8 = r0 + 8 * DH;
        #pragma unroll
        for (int kt = 0; kt < 2; kt++) {
            int c0 = 2 * tig + 16 * kt;
            float2 v00 = *(const float2*)(r0 + c0);
            float2 v10 = *(const float2*)(r8 + c0);
            float2 v01 = *(const float2*)(r0 + c0 + 8);
            float2 v11 = *(const float2*)(r8 + c0 + 8);
            Ah[kt][0] = pack_bf2(v00.x, v00.y, Al[kt][0]);
            Ah[kt][1] = pack_bf2(v10.x, v10.y, Al[kt][1]);
            Ah[kt][2] = pack_bf2(v01.x, v01.y, Al[kt][2]);
            Ah[kt][3] = pack_bf2(v11.x, v11.y, Al[kt][3]);
        }
    }
    __syncthreads();

    // accumulators init from bias (rows g and g+8 share cols)
    float acc[8][4];
    #pragma unroll
    for (int et = 0; et < 8; et++) {
        float2 bb = *(const float2*)(sbias + ehalf + 8 * et + 2 * tig);
        acc[et][0] = bb.x; acc[et][1] = bb.y;
        acc[et][2] = bb.x; acc[et][3] = bb.y;
    }

    // mma loop: 8 et x 2 kt x 3 products = 48 HMMA per warp
    #pragma unroll
    for (int et = 0; et < 8; et++) {
        int erow = (ehalf + 8 * et + g) * BPITCH;
        #pragma unroll
        for (int kt = 0; kt < 2; kt++) {
            uint32_t bh0 = sBh[erow + tig + 8 * kt];
            uint32_t bh1 = sBh[erow + tig + 4 + 8 * kt];
            uint32_t bl0 = sBl[erow + tig + 8 * kt];
            uint32_t bl1 = sBl[erow + tig + 4 + 8 * kt];
            mma16816(acc[et], Ah[kt], bh0, bh1);
            mma16816(acc[et], Ah[kt], bl0, bl1);
            mma16816(acc[et], Al[kt], bh0, bh1);
        }
    }

    // epilogue: streaming edge add + store (32B segments, all sectors used)
    {
        const float* eb = edge + ((size_t)n * NN + m_base + m0 + g) * DE
                          + ehalf + 2 * tig;
        float* ob = out + ((size_t)n * NN + m_base + m0 + g) * DE
                    + ehalf + 2 * tig;
        #pragma unroll
        for (int et = 0; et < 8; et++) {
            float2 e0 = __ldcs((const float2*)(eb + 8 * et));
            float2 e1 = __ldcs((const float2*)(eb + 8 * et + 8 * DE));
            __stcs((float2*)(ob + 8 * et),
                   make_float2(acc[et][0] + e0.x, acc[et][1] + e0.y));
            __stcs((float2*)(ob + 8 * et + 8 * DE),
                   make_float2(acc[et][2] + e1.x, acc[et][3] + e1.y));
        }
    }
}

// ---------------- launch ----------------
extern "C" void kernel_launch(void* const* d_in, const int* in_sizes, int n_in,
                              void* d_out, int out_size) {
    const float* node   = (const float*)d_in[0];
    const float* edge   = (const float*)d_in[1];
    const float* ln_w   = (const float*)d_in[2];
    const float* ln_b   = (const float*)d_in[3];
    const float* w_left = (const float*)d_in[4];
    const float* b_left = (const float*)d_in[5];
    const float* w_right= (const float*)d_in[6];
    const float* b_right= (const float*)d_in[7];
    const float* w_out  = (const float*)d_in[8];
    const float* b_out  = (const float*)d_in[9];
    float* out = (float*)d_out;

    p1_kernel<<<NN, 256>>>(node, ln_w, ln_b, w_left, b_left, w_right, b_right);
    p2_kernel<<<dim3(32, 16), 256>>>(w_out);
    outk_kernel<<<dim3(8, NN), 256>>>(edge, b_out, out);
}

// round 11
// speedup vs baseline: 1.0445x; 1.0445x over previous
#include <cuda_runtime.h>
#include <cstdint>

#define NN 512      // tokens
#define DN 256      // d_node
#define DE 128      // d_edge
#define DH 32       // d_head
#define LN_EPS 1e-5f

// Scratch (device globals: no allocation allowed)
__device__ float g_left[NN * DH];
__device__ float g_right[NN * DH];
__device__ float g_T[NN * DH * DE];   // [n][j][e] = [512][32][128]

// ---------------- packed f32x2 helpers (sm_103a) ----------------
__device__ __forceinline__ unsigned long long pk2(float lo, float hi) {
    unsigned long long r;
    asm("mov.b64 %0, {%1, %2};" : "=l"(r) : "f"(lo), "f"(hi));
    return r;
}
__device__ __forceinline__ void fma2(unsigned long long& d,
                                     unsigned long long a,
                                     unsigned long long b) {
    asm("fma.rn.f32x2 %0, %1, %2, %0;" : "+l"(d) : "l"(a), "l"(b));
}
__device__ __forceinline__ void upk2(unsigned long long v, float& lo, float& hi) {
    asm("mov.b64 {%0, %1}, %2;" : "=f"(lo), "=f"(hi) : "l"(v));
}

// ---------------- P1: LayerNorm + left/right projections ----------------
// One block per token (512 blocks x 256 threads). Fused sum/sumsq reduction.
// Proj loop: 8 independent accumulators to deepen the LDG chain.
__global__ void p1_kernel(const float* __restrict__ node,
                          const float* __restrict__ ln_w,
                          const float* __restrict__ ln_b,
                          const float* __restrict__ wl,
                          const float* __restrict__ bl,
                          const float* __restrict__ wr,
                          const float* __restrict__ br) {
    __shared__ float xs[DN];
    __shared__ float2 red[8];
    __shared__ float ps[4][64];

    int n = blockIdx.x;
    int tid = threadIdx.x;
    float v = node[n * DN + tid];

    float s = v, q = v * v;
    #pragma unroll
    for (int o = 16; o; o >>= 1) {
        s += __shfl_xor_sync(0xffffffffu, s, o);
        q += __shfl_xor_sync(0xffffffffu, q, o);
    }
    if ((tid & 31) == 0) red[tid >> 5] = make_float2(s, q);
    __syncthreads();
    float S = 0.f, Q = 0.f;
    #pragma unroll
    for (int i = 0; i < 8; i++) { S += red[i].x; Q += red[i].y; }
    float mu = S * (1.f / 256.f);
    float var = Q * (1.f / 256.f) - mu * mu;
    float rstd = rsqrtf(var + LN_EPS);

    xs[tid] = (v - mu) * rstd * ln_w[tid] + ln_b[tid];
    __syncthreads();

    int h = tid & 31;
    int sel = (tid >> 5) & 1;
    int part = tid >> 6;
    const float* __restrict__ w = sel ? wr : wl;
    int k0 = part * 64;
    float a[8];
    #pragma unroll
    for (int i = 0; i < 8; i++) a[i] = 0.f;
    #pragma unroll 2
    for (int k = 0; k < 64; k += 8) {
        #pragma unroll
        for (int i = 0; i < 8; i++)
            a[i] += xs[k0 + k + i] * __ldg(w + (k0 + k + i) * DH + h);
    }
    ps[part][sel * 32 + h] = ((a[0] + a[1]) + (a[2] + a[3]))
                           + ((a[4] + a[5]) + (a[6] + a[7]));
    __syncthreads();

    if (tid < 64) {
        float r = ps[0][tid] + ps[1][tid] + ps[2][tid] + ps[3][tid];
        if (tid < 32) g_left[n * DH + tid] = r + bl[tid];
        else          g_right[n * DH + (tid - 32)] = r + br[tid - 32];
    }
}

// ---------------- P2: T = left @ w_out (viewed [32][4096]) ----------------
__global__ void p2_kernel(const float* __restrict__ w_out) {
    __shared__ float As[32 * 32];

    int nb = blockIdx.y * 32;
    int cb = blockIdx.x * 128;
    int tid = threadIdx.x;

    {
        int row = tid >> 3, qq = tid & 7;
        *(float4*)&As[row * 32 + qq * 4] =
            *(const float4*)(g_left + (nb + row) * DH + qq * 4);
    }
    __syncthreads();

    int col = cb + (tid & 127);
    int nset = tid >> 7;
    float acc[16];
    #pragma unroll
    for (int r = 0; r < 16; r++) acc[r] = 0.f;

    #pragma unroll 4
    for (int i = 0; i < 32; i++) {
        float b = w_out[i * 4096 + col];
        #pragma unroll
        for (int r = 0; r < 16; r++)
            acc[r] += As[(nset * 16 + r) * 32 + i] * b;
    }

    #pragma unroll
    for (int r = 0; r < 16; r++)
        g_T[(nb + nset * 16 + r) * (DH * DE) + col] = acc[r];
}

// ---------------- Main kernel: out = edge + b_out + right @ T ----------------
// 64m x 128e tile, 256 threads, 4 blocks/SM (32 warps): independent blocks
// interleave load/compute/store phases. Per thread: 8m x 4e as 16 packed
// f32x2 accumulators initialized from bias; edge added in the epilogue
// (latency covered by sibling blocks). Register-lean for the 64-reg cap.
__global__ void __launch_bounds__(256, 4)
outk_kernel(const float* __restrict__ edge,
            const float* __restrict__ b_out,
            float* __restrict__ out) {
    __shared__ __align__(16) float sT[DH * DE];   // [j][e]   16 KB
    __shared__ __align__(16) float sR[DH * 64];   // [j][m]    8 KB

    int n = blockIdx.y;
    int m_base = blockIdx.x * 64;
    int tid = threadIdx.x;
    int lane = tid & 31;
    int w    = tid >> 5;          // 0..7
    int e0 = lane * 4;            // 4 e columns
    int mt = w * 8;               // 8 m rows per warp

    // fill sT (16 KB coalesced: 4 float4 per thread)
    {
        const float4* gT4 = (const float4*)(g_T + (size_t)n * (DH * DE));
        float4* sT4 = (float4*)sT;
        #pragma unroll
        for (int k = 0; k < 4; k++) sT4[tid + k * 256] = gT4[tid + k * 256];
    }
    // fill sR transposed: sR[j][ml] = right[m_base+ml][j]
    {
        int ml = tid & 63;
        int jq0 = tid >> 6;           // 0..3
        #pragma unroll
        for (int it = 0; it < 2; it++) {
            int jq = jq0 + it * 4;    // 0..7
            float4 r4 = *(const float4*)(g_right + (m_base + ml) * DH + jq * 4);
            sR[(jq * 4 + 0) * 64 + ml] = r4.x;
            sR[(jq * 4 + 1) * 64 + ml] = r4.y;
            sR[(jq * 4 + 2) * 64 + ml] = r4.z;
            sR[(jq * 4 + 3) * 64 + ml] = r4.w;
        }
    }

    // acc init from bias only (both m's of a pair share the e-column bias)
    float4 b4 = *(const float4*)(b_out + e0);
    unsigned long long bb0 = pk2(b4.x, b4.x);
    unsigned long long bb1 = pk2(b4.y, b4.y);
    unsigned long long bb2 = pk2(b4.z, b4.z);
    unsigned long long bb3 = pk2(b4.w, b4.w);
    unsigned long long acc[4][4];
    #pragma unroll
    for (int mp = 0; mp < 4; mp++) {
        acc[mp][0] = bb0; acc[mp][1] = bb1; acc[mp][2] = bb2; acc[mp][3] = bb3;
    }
    __syncthreads();

    // fma mainloop: 16 FFMA2 + 3 LDS per thread per j
    #pragma unroll 8
    for (int j = 0; j < DH; j++) {
        float4 t4 = *(const float4*)(sT + j * DE + e0);
        unsigned long long t0 = pk2(t4.x, t4.x);
        unsigned long long t1 = pk2(t4.y, t4.y);
        unsigned long long t2 = pk2(t4.z, t4.z);
        unsigned long long t3 = pk2(t4.w, t4.w);
        const ulonglong2* rj = (const ulonglong2*)(sR + j * 64 + mt);
        ulonglong2 rA = rj[0];   // m-pairs (0,1),(2,3)  (warp-uniform LDS)
        ulonglong2 rB = rj[1];   // m-pairs (4,5),(6,7)
        fma2(acc[0][0], rA.x, t0); fma2(acc[0][1], rA.x, t1);
        fma2(acc[0][2], rA.x, t2); fma2(acc[0][3], rA.x, t3);
        fma2(acc[1][0], rA.y, t0); fma2(acc[1][1], rA.y, t1);
        fma2(acc[1][2], rA.y, t2); fma2(acc[1][3], rA.y, t3);
        fma2(acc[2][0], rB.x, t0); fma2(acc[2][1], rB.x, t1);
        fma2(acc[2][2], rB.x, t2); fma2(acc[2][3], rB.x, t3);
        fma2(acc[3][0], rB.y, t0); fma2(acc[3][1], rB.y, t1);
        fma2(acc[3][2], rB.y, t2); fma2(acc[3][3], rB.y, t3);
    }

    // epilogue: edge add + store (streaming both ways; transient registers)
    const float* erow = edge + ((size_t)n * NN + m_base + mt) * DE + e0;
    float* orow = out + ((size_t)n * NN + m_base + mt) * DE + e0;
    #pragma unroll
    for (int mp = 0; mp < 4; mp++) {
        float4 ea = __ldcs((const float4*)(erow + (2 * mp) * DE));
        float4 eb = __ldcs((const float4*)(erow + (2 * mp + 1) * DE));
        float a0, c0, a1, c1, a2, c2, a3, c3;
        upk2(acc[mp][0], a0, c0);
        upk2(acc[mp][1], a1, c1);
        upk2(acc[mp][2], a2, c2);
        upk2(acc[mp][3], a3, c3);
        __stcs((float4*)(orow + (2 * mp) * DE),
               make_float4(a0 + ea.x, a1 + ea.y, a2 + ea.z, a3 + ea.w));
        __stcs((float4*)(orow + (2 * mp + 1) * DE),
               make_float4(c0 + eb.x, c1 + eb.y, c2 + eb.z, c3 + eb.w));
    }
}

// ---------------- launch ----------------
extern "C" void kernel_launch(void* const* d_in, const int* in_sizes, int n_in,
                              void* d_out, int out_size) {
    const float* node   = (const float*)d_in[0];
    const float* edge   = (const float*)d_in[1];
    const float* ln_w   = (const float*)d_in[2];
    const float* ln_b   = (const float*)d_in[3];
    const float* w_left = (const float*)d_in[4];
    const float* b_left = (const float*)d_in[5];
    const float* w_right= (const float*)d_in[6];
    const float* b_right= (const float*)d_in[7];
    const float* w_out  = (const float*)d_in[8];
    const float* b_out  = (const float*)d_in[9];
    float* out = (float*)d_out;

    p1_kernel<<<NN, 256>>>(node, ln_w, ln_b, w_left, b_left, w_right, b_right);
    p2_kernel<<<dim3(32, 16), 256>>>(w_out);
    outk_kernel<<<dim3(8, NN), 256>>>(edge, b_out, out);
}

// round 12
// speedup vs baseline: 1.1357x; 1.0874x over previous
#include <cuda_runtime.h>
#include <cstdint>

#define NN 512      // tokens
#define DN 256      // d_node
#define DE 128      // d_edge
#define DH 32       // d_head
#define LN_EPS 1e-5f

// Scratch (device globals: no allocation allowed)
__device__ float g_left[NN * DH];
__device__ float g_right[NN * DH];
__device__ float g_T[NN * DH * DE];   // [n][j][e] = [512][32][128]

// p1 dynamic smem: wl (8192 f) + wr (8192 f) + xs (256 f)
#define P1_SMEM_FLOATS (8192 + 8192 + 256)
#define P1_SMEM_BYTES  (P1_SMEM_FLOATS * 4)

// ---------------- packed f32x2 helpers (sm_103a) ----------------
__device__ __forceinline__ unsigned long long pk2(float lo, float hi) {
    unsigned long long r;
    asm("mov.b64 %0, {%1, %2};" : "=l"(r) : "f"(lo), "f"(hi));
    return r;
}
__device__ __forceinline__ void fma2(unsigned long long& d,
                                     unsigned long long a,
                                     unsigned long long b) {
    asm("fma.rn.f32x2 %0, %1, %2, %0;" : "+l"(d) : "l"(a), "l"(b));
}
__device__ __forceinline__ void upk2(unsigned long long v, float& lo, float& hi) {
    asm("mov.b64 {%0, %1}, %2;" : "=f"(lo), "=f"(hi) : "l"(v));
}

// ---------------- P1: LayerNorm + left/right projections ----------------
// One block per token (512 x 256). Weights staged into dynamic smem with
// bulk LDG.128 (high MLP) BEFORE the LN reductions; projection loop runs
// entirely out of smem (broadcast LDS + conflict-free LDS + FFMA).
__global__ void p1_kernel(const float* __restrict__ node,
                          const float* __restrict__ ln_w,
                          const float* __restrict__ ln_b,
                          const float* __restrict__ wl,
                          const float* __restrict__ bl,
                          const float* __restrict__ wr,
                          const float* __restrict__ br) {
    extern __shared__ __align__(16) float sw[];   // [wl 8192][wr 8192][xs 256]
    __shared__ float2 red[8];
    __shared__ float ps[4][64];

    float* swl = sw;
    float* swr = sw + 8192;
    float* xs  = sw + 16384;

    int n = blockIdx.x;
    int tid = threadIdx.x;

    // issue node load first
    float v = node[n * DN + tid];

    // stage weights: 8 float4 per thread per matrix (bulk, high MLP)
    {
        const float4* wl4 = (const float4*)wl;
        const float4* wr4 = (const float4*)wr;
        float4* sl4 = (float4*)swl;
        float4* sr4 = (float4*)swr;
        #pragma unroll
        for (int k = 0; k < 8; k++) {
            sl4[tid + k * 256] = wl4[tid + k * 256];
            sr4[tid + k * 256] = wr4[tid + k * 256];
        }
    }

    // fused sum + sumsq reduction (overlaps staging completion)
    float s = v, q = v * v;
    #pragma unroll
    for (int o = 16; o; o >>= 1) {
        s += __shfl_xor_sync(0xffffffffu, s, o);
        q += __shfl_xor_sync(0xffffffffu, q, o);
    }
    if ((tid & 31) == 0) red[tid >> 5] = make_float2(s, q);
    __syncthreads();
    float S = 0.f, Q = 0.f;
    #pragma unroll
    for (int i = 0; i < 8; i++) { S += red[i].x; Q += red[i].y; }
    float mu = S * (1.f / 256.f);
    float var = Q * (1.f / 256.f) - mu * mu;
    float rstd = rsqrtf(var + LN_EPS);

    xs[tid] = (v - mu) * rstd * ln_w[tid] + ln_b[tid];
    __syncthreads();

    // projections from smem: thread t -> (h, left/right, k-quarter)
    int h = tid & 31;
    int sel = (tid >> 5) & 1;
    int part = tid >> 6;
    const float* w = sel ? swr : swl;
    int k0 = part * 64;
    float a0 = 0.f, a1 = 0.f, a2 = 0.f, a3 = 0.f;
    #pragma unroll 4
    for (int k = 0; k < 64; k += 4) {
        a0 += xs[k0 + k + 0] * w[(k0 + k + 0) * DH + h];
        a1 += xs[k0 + k + 1] * w[(k0 + k + 1) * DH + h];
        a2 += xs[k0 + k + 2] * w[(k0 + k + 2) * DH + h];
        a3 += xs[k0 + k + 3] * w[(k0 + k + 3) * DH + h];
    }
    ps[part][sel * 32 + h] = (a0 + a1) + (a2 + a3);
    __syncthreads();

    if (tid < 64) {
        float r = ps[0][tid] + ps[1][tid] + ps[2][tid] + ps[3][tid];
        if (tid < 32) g_left[n * DH + tid] = r + bl[tid];
        else          g_right[n * DH + (tid - 32)] = r + br[tid - 32];
    }
}

// ---------------- P2: T = left @ w_out (viewed [32][4096]) ----------------
__global__ void p2_kernel(const float* __restrict__ w_out) {
    __shared__ float As[32 * 32];

    int nb = blockIdx.y * 32;
    int cb = blockIdx.x * 128;
    int tid = threadIdx.x;

    {
        int row = tid >> 3, qq = tid & 7;
        *(float4*)&As[row * 32 + qq * 4] =
            *(const float4*)(g_left + (nb + row) * DH + qq * 4);
    }
    __syncthreads();

    int col = cb + (tid & 127);
    int nset = tid >> 7;
    float acc[16];
    #pragma unroll
    for (int r = 0; r < 16; r++) acc[r] = 0.f;

    #pragma unroll 4
    for (int i = 0; i < 32; i++) {
        float b = w_out[i * 4096 + col];
        #pragma unroll
        for (int r = 0; r < 16; r++)
            acc[r] += As[(nset * 16 + r) * 32 + i] * b;
    }

    #pragma unroll
    for (int r = 0; r < 16; r++)
        g_T[(nb + nset * 16 + r) * (DH * DE) + col] = acc[r];
}

// ---------------- Main kernel: out = edge + b_out + right @ T ----------------
// R9 exact: 64m x 128e tile, 256 threads, 3 blocks/SM; edge loads issued
// FIRST (streaming), smem fills hide them; per thread 8m x 4e as 16 f32x2.
__global__ void __launch_bounds__(256, 3)
outk_kernel(const float* __restrict__ edge,
            const float* __restrict__ b_out,
            float* __restrict__ out) {
    __shared__ __align__(16) float sT[DH * DE];   // [j][e]   16 KB
    __shared__ __align__(16) float sR[DH * 64];   // [j][m]    8 KB

    int n = blockIdx.y;
    int m_base = blockIdx.x * 64;
    int tid = threadIdx.x;
    int lane = tid & 31;
    int w    = tid >> 5;          // 0..7
    int e0 = lane * 4;            // 4 e columns
    int mt = w * 8;               // 8 m rows per warp

    // 1) edge loads first (streaming; in flight during smem fills)
    const float4* ep = (const float4*)(edge + ((size_t)n * NN + m_base + mt) * DE + e0);
    float4 ev[8];
    #pragma unroll
    for (int r = 0; r < 8; r++) ev[r] = __ldcs(ep + r * (DE / 4));

    // 2) fill sT (16 KB coalesced: 4 float4 per thread)
    {
        const float4* gT4 = (const float4*)(g_T + (size_t)n * (DH * DE));
        float4* sT4 = (float4*)sT;
        #pragma unroll
        for (int k = 0; k < 4; k++) sT4[tid + k * 256] = gT4[tid + k * 256];
    }
    // 3) fill sR transposed: sR[j][ml] = right[m_base+ml][j]
    {
        int ml = tid & 63;
        int jq0 = tid >> 6;           // 0..3
        #pragma unroll
        for (int it = 0; it < 2; it++) {
            int jq = jq0 + it * 4;    // 0..7
            float4 r4 = *(const float4*)(g_right + (m_base + ml) * DH + jq * 4);
            sR[(jq * 4 + 0) * 64 + ml] = r4.x;
            sR[(jq * 4 + 1) * 64 + ml] = r4.y;
            sR[(jq * 4 + 2) * 64 + ml] = r4.z;
            sR[(jq * 4 + 3) * 64 + ml] = r4.w;
        }
    }
    __syncthreads();

    // 4) acc init from edge + bias
    float4 b4 = *(const float4*)(b_out + e0);
    unsigned long long acc[4][4];
    #pragma unroll
    for (int mp = 0; mp < 4; mp++) {
        float4 ea = ev[2 * mp];
        float4 eb = ev[2 * mp + 1];
        acc[mp][0] = pk2(ea.x + b4.x, eb.x + b4.x);
        acc[mp][1] = pk2(ea.y + b4.y, eb.y + b4.y);
        acc[mp][2] = pk2(ea.z + b4.z, eb.z + b4.z);
        acc[mp][3] = pk2(ea.w + b4.w, eb.w + b4.w);
    }

    // 5) fma mainloop: 16 FFMA2 + 3 LDS per thread per j
    #pragma unroll 8
    for (int j = 0; j < DH; j++) {
        float4 t4 = *(const float4*)(sT + j * DE + e0);
        unsigned long long t0 = pk2(t4.x, t4.x);
        unsigned long long t1 = pk2(t4.y, t4.y);
        unsigned long long t2 = pk2(t4.z, t4.z);
        unsigned long long t3 = pk2(t4.w, t4.w);
        const ulonglong2* rj = (const ulonglong2*)(sR + j * 64 + mt);
        ulonglong2 rA = rj[0];   // m-pairs (0,1),(2,3)  (warp-uniform LDS)
        ulonglong2 rB = rj[1];   // m-pairs (4,5),(6,7)
        fma2(acc[0][0], rA.x, t0); fma2(acc[0][1], rA.x, t1);
        fma2(acc[0][2], rA.x, t2); fma2(acc[0][3], rA.x, t3);
        fma2(acc[1][0], rA.y, t0); fma2(acc[1][1], rA.y, t1);
        fma2(acc[1][2], rA.y, t2); fma2(acc[1][3], rA.y, t3);
        fma2(acc[2][0], rB.x, t0); fma2(acc[2][1], rB.x, t1);
        fma2(acc[2][2], rB.x, t2); fma2(acc[2][3], rB.x, t3);
        fma2(acc[3][0], rB.y, t0); fma2(acc[3][1], rB.y, t1);
        fma2(acc[3][2], rB.y, t2); fma2(acc[3][3], rB.y, t3);
    }

    // 6) epilogue: streaming STG.128
    float* orow = out + ((size_t)n * NN + m_base + mt) * DE + e0;
    #pragma unroll
    for (int mp = 0; mp < 4; mp++) {
        float a0, c0, a1, c1, a2, c2, a3, c3;
        upk2(acc[mp][0], a0, c0);
        upk2(acc[mp][1], a1, c1);
        upk2(acc[mp][2], a2, c2);
        upk2(acc[mp][3], a3, c3);
        __stcs((float4*)(orow + (2 * mp) * DE),     make_float4(a0, a1, a2, a3));
        __stcs((float4*)(orow + (2 * mp + 1) * DE), make_float4(c0, c1, c2, c3));
    }
}

// ---------------- launch ----------------
extern "C" void kernel_launch(void* const* d_in, const int* in_sizes, int n_in,
                              void* d_out, int out_size) {
    const float* node   = (const float*)d_in[0];
    const float* edge   = (const float*)d_in[1];
    const float* ln_w   = (const float*)d_in[2];
    const float* ln_b   = (const float*)d_in[3];
    const float* w_left = (const float*)d_in[4];
    const float* b_left = (const float*)d_in[5];
    const float* w_right= (const float*)d_in[6];
    const float* b_right= (const float*)d_in[7];
    const float* w_out  = (const float*)d_in[8];
    const float* b_out  = (const float*)d_in[9];
    float* out = (float*)d_out;

    // host-side attribute set (not stream-ordered; capture-safe, idempotent)
    cudaFuncSetAttribute(p1_kernel,
                         cudaFuncAttributeMaxDynamicSharedMemorySize,
                         P1_SMEM_BYTES);

    p1_kernel<<<NN, 256, P1_SMEM_BYTES>>>(node, ln_w, ln_b, w_left, b_left,
                                          w_right, b_right);
    p2_kernel<<<dim3(32, 16), 256>>>(w_out);
    outk_kernel<<<dim3(8, NN), 256>>>(edge, b_out, out);
}

// round 14
// speedup vs baseline: 1.2114x; 1.0667x over previous
#include <cuda_runtime.h>
#include <cstdint>

#define NN 512      // tokens
#define DN 256      // d_node
#define DE 128      // d_edge
#define DH 32       // d_head
#define LN_EPS 1e-5f

// Scratch (device globals: no allocation allowed)
__device__ float g_left[NN * DH];
__device__ float g_right[NN * DH];
__device__ float g_T[NN * DH * DE];   // [n][j][e] = [512][32][128]

// ---------------- packed f32x2 helpers (sm_103a) ----------------
__device__ __forceinline__ unsigned long long pk2(float lo, float hi) {
    unsigned long long r;
    asm("mov.b64 %0, {%1, %2};" : "=l"(r) : "f"(lo), "f"(hi));
    return r;
}
__device__ __forceinline__ void fma2(unsigned long long& d,
                                     unsigned long long a,
                                     unsigned long long b) {
    asm("fma.rn.f32x2 %0, %1, %2, %0;" : "+l"(d) : "l"(a), "l"(b));
}
__device__ __forceinline__ void upk2(unsigned long long v, float& lo, float& hi) {
    asm("mov.b64 {%0, %1}, %2;" : "=f"(lo), "=f"(hi) : "l"(v));
}

// ---------------- cp.async helpers ----------------
__device__ __forceinline__ void cp_async16(unsigned smem_addr, const void* gptr) {
    asm volatile("cp.async.cg.shared.global [%0], [%1], 16;"
                 :: "r"(smem_addr), "l"(gptr));
}
__device__ __forceinline__ void cp_commit() {
    asm volatile("cp.async.commit_group;");
}
__device__ __forceinline__ void cp_wait_all() {
    asm volatile("cp.async.wait_group 0;");
}

// ---------------- P1: LayerNorm + left/right projections (R4 proven) ------
__global__ void p1_kernel(const float* __restrict__ node,
                          const float* __restrict__ ln_w,
                          const float* __restrict__ ln_b,
                          const float* __restrict__ wl,
                          const float* __restrict__ bl,
                          const float* __restrict__ wr,
                          const float* __restrict__ br) {
    __shared__ float xs[DN];
    __shared__ float2 red[8];
    __shared__ float ps[4][64];

    int n = blockIdx.x;
    int tid = threadIdx.x;
    float v = node[n * DN + tid];

    float s = v, q = v * v;
    #pragma unroll
    for (int o = 16; o; o >>= 1) {
        s += __shfl_xor_sync(0xffffffffu, s, o);
        q += __shfl_xor_sync(0xffffffffu, q, o);
    }
    if ((tid & 31) == 0) red[tid >> 5] = make_float2(s, q);
    __syncthreads();
    float S = 0.f, Q = 0.f;
    #pragma unroll
    for (int i = 0; i < 8; i++) { S += red[i].x; Q += red[i].y; }
    float mu = S * (1.f / 256.f);
    float var = Q * (1.f / 256.f) - mu * mu;
    float rstd = rsqrtf(var + LN_EPS);

    xs[tid] = (v - mu) * rstd * ln_w[tid] + ln_b[tid];
    __syncthreads();

    int h = tid & 31;
    int sel = (tid >> 5) & 1;
    int part = tid >> 6;
    const float* __restrict__ w = sel ? wr : wl;
    int k0 = part * 64;
    float a0 = 0.f, a1 = 0.f, a2 = 0.f, a3 = 0.f;
    #pragma unroll 4
    for (int k = 0; k < 64; k += 4) {
        a0 += xs[k0 + k + 0] * w[(k0 + k + 0) * DH + h];
        a1 += xs[k0 + k + 1] * w[(k0 + k + 1) * DH + h];
        a2 += xs[k0 + k + 2] * w[(k0 + k + 2) * DH + h];
        a3 += xs[k0 + k + 3] * w[(k0 + k + 3) * DH + h];
    }
    ps[part][sel * 32 + h] = (a0 + a1) + (a2 + a3);
    __syncthreads();

    if (tid < 64) {
        float r = ps[0][tid] + ps[1][tid] + ps[2][tid] + ps[3][tid];
        if (tid < 32) g_left[n * DH + tid] = r + bl[tid];
        else          g_right[n * DH + (tid - 32)] = r + br[tid - 32];
    }
}

// ---------------- P2: T = left @ w_out (viewed [32][4096]) ----------------
__global__ void p2_kernel(const float* __restrict__ w_out) {
    __shared__ float As[32 * 32];

    int nb = blockIdx.y * 32;
    int cb = blockIdx.x * 128;
    int tid = threadIdx.x;

    {
        int row = tid >> 3, qq = tid & 7;
        *(float4*)&As[row * 32 + qq * 4] =
            *(const float4*)(g_left + (nb + row) * DH + qq * 4);
    }
    __syncthreads();

    int col = cb + (tid & 127);
    int nset = tid >> 7;
    float acc[16];
    #pragma unroll
    for (int r = 0; r < 16; r++) acc[r] = 0.f;

    #pragma unroll 4
    for (int i = 0; i < 32; i++) {
        float b = w_out[i * 4096 + col];
        #pragma unroll
        for (int r = 0; r < 16; r++)
            acc[r] += As[(nset * 16 + r) * 32 + i] * b;
    }

    #pragma unroll
    for (int r = 0; r < 16; r++)
        g_T[(nb + nset * 16 + r) * (DH * DE) + col] = acc[r];
}

// ---------------- Main kernel: out = edge + b_out + right @ T ----------------
// R9 structure (64m x 128e, 256 threads, 3 blocks/SM) but 2 consecutive n per
// block: sR filled once, sT double-buffered via cp.async (T[n+1] prefetch
// hidden under fma(n0)); edge[n] loads issued first each iteration.
// FIX vs R13: 4 cp.async x 16B per thread (256 thr x 64 B = full 16 KB tile).
__global__ void __launch_bounds__(256, 3)
outk_kernel(const float* __restrict__ edge,
            const float* __restrict__ b_out,
            float* __restrict__ out) {
    __shared__ __align__(16) float sT[2][DH * DE];  // [buf][j][e]  32 KB
    __shared__ __align__(16) float sR[DH * 64];     // [j][m]        8 KB

    int n0 = blockIdx.y * 2;
    int m_base = blockIdx.x * 64;
    int tid = threadIdx.x;
    int lane = tid & 31;
    int w    = tid >> 5;          // 0..7
    int e0 = lane * 4;            // 4 e columns
    int mt = w * 8;               // 8 m rows per warp

    unsigned sT1_base = (unsigned)__cvta_generic_to_shared(&sT[1][0]);

    // 1) edge[n0] loads first (streaming; in flight during smem fills)
    float4 ev[8];
    {
        const float4* ep = (const float4*)(edge + ((size_t)n0 * NN + m_base + mt) * DE + e0);
        #pragma unroll
        for (int r = 0; r < 8; r++) ev[r] = __ldcs(ep + r * (DE / 4));
    }

    // 2) fill sT[0] with T[n0] (regular loads) + prefetch full T[n0+1] tile
    {
        const float4* gT4 = (const float4*)(g_T + (size_t)n0 * (DH * DE));
        float4* sT4 = (float4*)&sT[0][0];
        #pragma unroll
        for (int k = 0; k < 4; k++) sT4[tid + k * 256] = gT4[tid + k * 256];

        const char* g1 = (const char*)(g_T + (size_t)(n0 + 1) * (DH * DE)) + tid * 16;
        #pragma unroll
        for (int k = 0; k < 4; k++)
            cp_async16(sT1_base + tid * 16 + k * 4096, g1 + k * 4096);
        cp_commit();
    }
    // 3) fill sR transposed: sR[j][ml] = right[m_base+ml][j]  (once)
    {
        int ml = tid & 63;
        int jq0 = tid >> 6;           // 0..3
        #pragma unroll
        for (int it = 0; it < 2; it++) {
            int jq = jq0 + it * 4;    // 0..7
            float4 r4 = *(const float4*)(g_right + (m_base + ml) * DH + jq * 4);
            sR[(jq * 4 + 0) * 64 + ml] = r4.x;
            sR[(jq * 4 + 1) * 64 + ml] = r4.y;
            sR[(jq * 4 + 2) * 64 + ml] = r4.z;
            sR[(jq * 4 + 3) * 64 + ml] = r4.w;
        }
    }
    __syncthreads();

    float4 b4 = *(const float4*)(b_out + e0);

    #pragma unroll
    for (int it = 0; it < 2; it++) {
        int n = n0 + it;

        // acc init from edge + bias
        unsigned long long acc[4][4];
        #pragma unroll
        for (int mp = 0; mp < 4; mp++) {
            float4 ea = ev[2 * mp];
            float4 eb = ev[2 * mp + 1];
            acc[mp][0] = pk2(ea.x + b4.x, eb.x + b4.x);
            acc[mp][1] = pk2(ea.y + b4.y, eb.y + b4.y);
            acc[mp][2] = pk2(ea.z + b4.z, eb.z + b4.z);
            acc[mp][3] = pk2(ea.w + b4.w, eb.w + b4.w);
        }

        // fma mainloop: 16 FFMA2 + 3 LDS per thread per j
        const float* sTb = &sT[it][0];
        #pragma unroll 8
        for (int j = 0; j < DH; j++) {
            float4 t4 = *(const float4*)(sTb + j * DE + e0);
            unsigned long long t0 = pk2(t4.x, t4.x);
            unsigned long long t1 = pk2(t4.y, t4.y);
            unsigned long long t2 = pk2(t4.z, t4.z);
            unsigned long long t3 = pk2(t4.w, t4.w);
            const ulonglong2* rj = (const ulonglong2*)(sR + j * 64 + mt);
            ulonglong2 rA = rj[0];
            ulonglong2 rB = rj[1];
            fma2(acc[0][0], rA.x, t0); fma2(acc[0][1], rA.x, t1);
            fma2(acc[0][2], rA.x, t2); fma2(acc[0][3], rA.x, t3);
            fma2(acc[1][0], rA.y, t0); fma2(acc[1][1], rA.y, t1);
            fma2(acc[1][2], rA.y, t2); fma2(acc[1][3], rA.y, t3);
            fma2(acc[2][0], rB.x, t0); fma2(acc[2][1], rB.x, t1);
            fma2(acc[2][2], rB.x, t2); fma2(acc[2][3], rB.x, t3);
            fma2(acc[3][0], rB.y, t0); fma2(acc[3][1], rB.y, t1);
            fma2(acc[3][2], rB.y, t2); fma2(acc[3][3], rB.y, t3);
        }

        // epilogue: streaming STG.128
        float* orow = out + ((size_t)n * NN + m_base + mt) * DE + e0;
        #pragma unroll
        for (int mp = 0; mp < 4; mp++) {
            float a0, c0, a1, c1, a2, c2, a3, c3;
            upk2(acc[mp][0], a0, c0);
            upk2(acc[mp][1], a1, c1);
            upk2(acc[mp][2], a2, c2);
            upk2(acc[mp][3], a3, c3);
            __stcs((float4*)(orow + (2 * mp) * DE),     make_float4(a0, a1, a2, a3));
            __stcs((float4*)(orow + (2 * mp + 1) * DE), make_float4(c0, c1, c2, c3));
        }

        // prep next iteration: edge[n+1] loads + wait for prefetched sT[1]
        if (it == 0) {
            const float4* ep = (const float4*)(edge + ((size_t)(n0 + 1) * NN + m_base + mt) * DE + e0);
            #pragma unroll
            for (int r = 0; r < 8; r++) ev[r] = __ldcs(ep + r * (DE / 4));
            cp_wait_all();
            __syncthreads();
        }
    }
}

// ---------------- launch ----------------
extern "C" void kernel_launch(void* const* d_in, const int* in_sizes, int n_in,
                              void* d_out, int out_size) {
    const float* node   = (const float*)d_in[0];
    const float* edge   = (const float*)d_in[1];
    const float* ln_w   = (const float*)d_in[2];
    const float* ln_b   = (const float*)d_in[3];
    const float* w_left = (const float*)d_in[4];
    const float* b_left = (const float*)d_in[5];
    const float* w_right= (const float*)d_in[6];
    const float* b_right= (const float*)d_in[7];
    const float* w_out  = (const float*)d_in[8];
    const float* b_out  = (const float*)d_in[9];
    float* out = (float*)d_out;

    p1_kernel<<<NN, 256>>>(node, ln_w, ln_b, w_left, b_left, w_right, b_right);
    p2_kernel<<<dim3(32, 16), 256>>>(w_out);
    outk_kernel<<<dim3(8, NN / 2), 256>>>(edge, b_out, out);
}